// round 7
// baseline (speedup 1.0000x reference)
#include <cuda_runtime.h>
#include <cuda_bf16.h>
#include <math_constants.h>
#include <cstdint>

// ---------------------------------------------------------------------------
//   x: [4,256,64,64] f32; w_qkv:[768,256]; w_pe:[256,1,7,7]; w_proj:[256,256]
//   out: [4,256,64,64] f32.  Area attention: 16 strips x 8 heads, 1024x1024x32.
//   All matmuls: mma.sync.m16n8k8.tf32 (cvt.rna). Attention: 4 warps x m32,
//   shared K/V fragments across m-groups, no-max softmax.
// ---------------------------------------------------------------------------

#define NGLOB 16384
#define CIN   256
#define C3    768

__device__ float g_qkv[C3 * NGLOB];   // rows: h*96 + {0:q,32:k,64:v} + d
__device__ float g_att[CIN * NGLOB];
__device__ float g_t  [CIN * NGLOB];

__device__ __forceinline__ unsigned f2tf(float x) {
    unsigned r;
    asm("cvt.rna.tf32.f32 %0, %1;" : "=r"(r) : "f"(x));
    return r;
}

__device__ __forceinline__ void mma8(float* c, unsigned a0, unsigned a1,
                                     unsigned a2, unsigned a3,
                                     unsigned b0, unsigned b1) {
    asm volatile(
        "mma.sync.aligned.m16n8k8.row.col.f32.tf32.tf32.f32 "
        "{%0,%1,%2,%3},{%4,%5,%6,%7},{%8,%9},{%0,%1,%2,%3};\n"
        : "+f"(c[0]), "+f"(c[1]), "+f"(c[2]), "+f"(c[3])
        : "r"(a0), "r"(a1), "r"(a2), "r"(a3), "r"(b0), "r"(b1));
}

// ---------------------------------------------------------------------------
// TF32 GEMM (round-3 proven version): fragment-major, double-buffered.
// dst[b*db + o*dc + n] = bias[o] + sum_k w[o][k]*src[b*sb + k*sk + n]
// ---------------------------------------------------------------------------
#define GA_WORDS (64 * 66)
#define GBUF     (2 * GA_WORDS)
#define GSMEM_BYTES (2 * GBUF * 4)

__global__ void __launch_bounds__(256) gemm_tf32_kernel(
    const float* __restrict__ w, const float* __restrict__ bias,
    const float* __restrict__ src, int sb, int sk,
    float* __restrict__ dst, int db, int dc)
{
    extern __shared__ unsigned dynsm[];
    const int tid = threadIdx.x;
    const int L = tid & 31;
    const int ww = tid >> 5;
    const int wm = ww >> 2, wn = ww & 3;
    const int m0g = blockIdx.y * 128;
    const int ng0 = blockIdx.x * 128;
    const int b = ng0 >> 12, n0 = ng0 & 4095;

    const int lm = tid >> 1, lk = (tid & 1) * 16;
    const int aq = lm >> 4, arr = lm & 7, ass = (lm >> 3) & 1;
    const int bk = tid >> 3, bn0 = (tid & 7) * 16;
    const int bt = bk >> 3, ba4 = bk & 3, bu = (bk >> 2) & 1;

    float c[4][4][4];
#pragma unroll
    for (int q = 0; q < 4; q++)
#pragma unroll
        for (int f = 0; f < 4; f++)
#pragma unroll
            for (int j = 0; j < 4; j++) c[q][f][j] = 0.f;

    float4 areg[4], breg[4];

    auto ldAB = [&](int kb) {
        const float* ap = w + (size_t)(m0g + lm) * CIN + kb + lk;
        areg[0] = *(const float4*)ap;
        areg[1] = *(const float4*)(ap + 4);
        areg[2] = *(const float4*)(ap + 8);
        areg[3] = *(const float4*)(ap + 12);
        const float* bp = src + (size_t)b * sb + (size_t)(kb + bk) * sk + n0 + bn0;
        breg[0] = *(const float4*)bp;
        breg[1] = *(const float4*)(bp + 4);
        breg[2] = *(const float4*)(bp + 8);
        breg[3] = *(const float4*)(bp + 12);
    };

    auto stAB = [&](unsigned* buf) {
        unsigned* As = buf;
        unsigned* Bs = buf + GA_WORDS;
#pragma unroll
        for (int j = 0; j < 4; j++) {
            float va[4] = {areg[j].x, areg[j].y, areg[j].z, areg[j].w};
            float vb[4] = {breg[j].x, breg[j].y, breg[j].z, breg[j].w};
#pragma unroll
            for (int l = 0; l < 4; l++) {
                const int kk = lk + j * 4 + l;
                const int t = kk >> 3, a4 = kk & 3, u = (kk >> 2) & 1;
                As[(aq * 8 + t * 2 + u) * 66 + (arr * 4 + a4) * 2 + ass] = f2tf(va[l]);
                const int n = bn0 + j * 4 + l;
                const int wnn = n >> 5, f = (n >> 3) & 3, r = n & 7;
                Bs[((bt * 4 + f) * 4 + wnn) * 66 + (r * 4 + ba4) * 2 + bu] = f2tf(vb[l]);
            }
        }
    };

    auto comp = [&](const unsigned* buf) {
        const unsigned* As = buf;
        const unsigned* Bs = buf + GA_WORDS;
#pragma unroll
        for (int t = 0; t < 4; t++) {
            uint2 aLo[4], aHi[4];
#pragma unroll
            for (int q = 0; q < 4; q++) {
                const unsigned* p0 = As + ((wm * 4 + q) * 8 + t * 2) * 66 + L * 2;
                aLo[q] = *(const uint2*)p0;
                aHi[q] = *(const uint2*)(p0 + 66);
            }
#pragma unroll
            for (int f = 0; f < 4; f++) {
                uint2 bb = *(const uint2*)(Bs + ((t * 4 + f) * 4 + wn) * 66 + L * 2);
#pragma unroll
                for (int q = 0; q < 4; q++)
                    mma8(c[q][f], aLo[q].x, aLo[q].y, aHi[q].x, aHi[q].y, bb.x, bb.y);
            }
        }
    };

    ldAB(0);
    stAB(dynsm);
    __syncthreads();
#pragma unroll 1
    for (int kt = 0; kt < 8; kt++) {
        if (kt < 7) ldAB((kt + 1) * 32);
        comp(dynsm + (kt & 1) * GBUF);
        if (kt < 7) stAB(dynsm + ((kt + 1) & 1) * GBUF);
        __syncthreads();
    }

    const int r = L >> 2, a4 = L & 3;
#pragma unroll
    for (int q = 0; q < 4; q++) {
        const int o = m0g + wm * 64 + 16 * q + r;
        const float bo0 = bias[o];
        const float bo1 = bias[o + 8];
#pragma unroll
        for (int f = 0; f < 4; f++) {
            const int col = n0 + wn * 32 + 8 * f + 2 * a4;
            float2 v0 = make_float2(c[q][f][0] + bo0, c[q][f][1] + bo0);
            float2 v1 = make_float2(c[q][f][2] + bo1, c[q][f][3] + bo1);
            *(float2*)(dst + (size_t)b * db + (size_t)o * dc + col) = v0;
            *(float2*)(dst + (size_t)b * db + (size_t)(o + 8) * dc + col) = v1;
        }
    }
}

// ---------------------------------------------------------------------------
// Flash attention v2: 4 warps x m32, 128 threads, double-buffered K/V.
// K groups (f*4+t), V groups (t*4+g); group stride 72 words (16B-aligned).
// Q fragment-major (stride 66) staged in buf1 then held in registers.
// ---------------------------------------------------------------------------
#define KV_WORDS (32 * 72)       // 2304
#define ABUF     (2 * KV_WORDS)  // 4608 per buffer (K then V)

__global__ void __launch_bounds__(128, 2) attn_kernel()
{
    __shared__ unsigned sm[2 * ABUF];   // 36864 B

    const int tid = threadIdx.x;
    const int L = tid & 31;
    const int wrp = tid >> 5;           // 0..3, warp handles rows [wrp*32, wrp*32+32)
    const int r = L >> 2, a4 = L & 3;
    const int qt = blockIdx.x, h = blockIdx.y, ba = blockIdx.z;
    const int colbase = (ba >> 2) * 4096 + (ba & 3) * 1024;
    const int qcol = colbase + qt * 128;
    const float scale = 0.17677669529663687f;  // 1/sqrt(32)

    // ---- stage Q fragment-major into buf1 region ----
    {
        const int d = tid >> 2;             // 0..31
        const int i0 = (tid & 3) * 32;      // 32 i's per thread
        const int t = d >> 3, qa4 = d & 3, u = (d >> 2) & 1;
        const float* srcq = g_qkv + (size_t)(h * 96 + d) * NGLOB + qcol + i0;
        unsigned* Qs = sm + ABUF;
#pragma unroll
        for (int ii = 0; ii < 32; ii++) {
            const int i = i0 + ii;
            const int qp = i >> 4, s = (i >> 3) & 1, rr = i & 7;
            Qs[(qp * 8 + t * 2 + u) * 66 + (rr * 4 + qa4) * 2 + s] = f2tf(srcq[ii] * scale);
        }
    }

    // K/V loader geometry: d = tid>>2 (0..31), j0 = (tid&3)*16 (16 j's)
    const int ld_d = tid >> 2;
    const int ld_j0 = (tid & 3) * 16;
    const int kt_ = ld_d >> 3, ka4 = ld_d & 3, ku = (ld_d >> 2) & 1;
    const int vg = ld_d >> 3, vr = ld_d & 7;
    const float* kbase = g_qkv + (size_t)(h * 96 + 32 + ld_d) * NGLOB + colbase + ld_j0;
    const float* vbase = kbase + (size_t)32 * NGLOB;

    float4 kR[4], vR[4];

    auto ldKV = [&](int jt) {
        const float* kp = kbase + jt * 64;
        const float* vp = vbase + jt * 64;
#pragma unroll
        for (int q = 0; q < 4; q++) {
            kR[q] = *(const float4*)(kp + 4 * q);
            vR[q] = *(const float4*)(vp + 4 * q);
        }
    };

    auto stKV = [&](unsigned* buf) {
        unsigned* K = buf;
        unsigned* V = buf + KV_WORDS;
        const float* kv = (const float*)kR;
#pragma unroll
        for (int jj = 0; jj < 16; jj++) {
            const int j = ld_j0 + jj;
            K[((j >> 3) * 4 + kt_) * 72 + (j & 7) * 8 + ka4 * 2 + ku] = f2tf(kv[jj]);
        }
        const float* vv = (const float*)vR;
#pragma unroll
        for (int blk = 0; blk < 2; blk++) {
            const int vt = (ld_j0 >> 3) + blk;
            uint4 p0 = make_uint4(f2tf(vv[blk * 8 + 0]), f2tf(vv[blk * 8 + 4]),
                                  f2tf(vv[blk * 8 + 1]), f2tf(vv[blk * 8 + 5]));
            uint4 p1 = make_uint4(f2tf(vv[blk * 8 + 2]), f2tf(vv[blk * 8 + 6]),
                                  f2tf(vv[blk * 8 + 3]), f2tf(vv[blk * 8 + 7]));
            unsigned* vd = V + (vt * 4 + vg) * 72 + vr * 8;
            *(uint4*)vd = p0;
            *(uint4*)(vd + 4) = p1;
        }
    };

    // stage K/V jt=0 into buf0
    ldKV(0);
    stKV(sm);
    __syncthreads();

    // ---- Q fragments to registers: 2 m-groups per warp ----
    unsigned qf[2][4][4];
    {
        const unsigned* Qs = sm + ABUF;
#pragma unroll
        for (int g2 = 0; g2 < 2; g2++) {
            const int qp = wrp * 2 + g2;
#pragma unroll
            for (int t = 0; t < 4; t++) {
                uint2 lo = *(const uint2*)(Qs + (qp * 8 + t * 2) * 66 + L * 2);
                uint2 hi = *(const uint2*)(Qs + (qp * 8 + t * 2 + 1) * 66 + L * 2);
                qf[g2][t][0] = lo.x; qf[g2][t][1] = lo.y;
                qf[g2][t][2] = hi.x; qf[g2][t][3] = hi.y;
            }
        }
    }
    __syncthreads();

    float l0[2], l1[2];
    l0[0] = l0[1] = l1[0] = l1[1] = 0.f;
    float o[2][4][4];
#pragma unroll
    for (int g2 = 0; g2 < 2; g2++)
#pragma unroll
        for (int g = 0; g < 4; g++)
#pragma unroll
            for (int j = 0; j < 4; j++) o[g2][g][j] = 0.f;

    const int src1 = (L & ~3) | (a4 >> 1);
    const int src2 = src1 | 2;
    const bool odd = (a4 & 1);

#pragma unroll 1
    for (int jt = 0; jt < 16; jt++) {
        if (jt < 15) ldKV(jt + 1);
        const unsigned* K = sm + (jt & 1) * ABUF;
        const unsigned* V = K + KV_WORDS;

        // ---- S = Q K^T : K fragment shared across both m-groups ----
        float c[2][8][4];
#pragma unroll
        for (int g2 = 0; g2 < 2; g2++)
#pragma unroll
            for (int f = 0; f < 8; f++)
#pragma unroll
                for (int j = 0; j < 4; j++) c[g2][f][j] = 0.f;

#pragma unroll
        for (int t = 0; t < 4; t++) {
#pragma unroll
            for (int f = 0; f < 8; f++) {
                uint2 kb2 = *(const uint2*)(K + (f * 4 + t) * 72 + L * 2);
                mma8(c[0][f], qf[0][t][0], qf[0][t][1], qf[0][t][2], qf[0][t][3],
                     kb2.x, kb2.y);
                mma8(c[1][f], qf[1][t][0], qf[1][t][1], qf[1][t][2], qf[1][t][3],
                     kb2.x, kb2.y);
            }
        }

        // ---- no-max softmax: exp + per-thread partial sums ----
#pragma unroll
        for (int g2 = 0; g2 < 2; g2++)
#pragma unroll
            for (int f = 0; f < 8; f++) {
                c[g2][f][0] = __expf(c[g2][f][0]); l0[g2] += c[g2][f][0];
                c[g2][f][1] = __expf(c[g2][f][1]); l0[g2] += c[g2][f][1];
                c[g2][f][2] = __expf(c[g2][f][2]); l1[g2] += c[g2][f][2];
                c[g2][f][3] = __expf(c[g2][f][3]); l1[g2] += c[g2][f][3];
            }

        // ---- O += P V : V fragments shared across both m-groups ----
#pragma unroll
        for (int t = 0; t < 8; t++) {
            uint2 vb[4];
#pragma unroll
            for (int g = 0; g < 4; g++)
                vb[g] = *(const uint2*)(V + (t * 4 + g) * 72 + L * 2);
#pragma unroll
            for (int g2 = 0; g2 < 2; g2++) {
                unsigned p0 = f2tf(c[g2][t][0]);
                unsigned p1 = f2tf(c[g2][t][1]);
                unsigned p2 = f2tf(c[g2][t][2]);
                unsigned p3 = f2tf(c[g2][t][3]);
                unsigned u0 = __shfl_sync(0xffffffffu, p0, src1);
                unsigned u1 = __shfl_sync(0xffffffffu, p1, src1);
                unsigned u2 = __shfl_sync(0xffffffffu, p2, src1);
                unsigned u3 = __shfl_sync(0xffffffffu, p3, src1);
                unsigned w0 = __shfl_sync(0xffffffffu, p0, src2);
                unsigned w1 = __shfl_sync(0xffffffffu, p1, src2);
                unsigned w2 = __shfl_sync(0xffffffffu, p2, src2);
                unsigned w3 = __shfl_sync(0xffffffffu, p3, src2);
                unsigned a0 = odd ? u1 : u0;
                unsigned a1 = odd ? u3 : u2;
                unsigned a2 = odd ? w1 : w0;
                unsigned a3 = odd ? w3 : w2;
#pragma unroll
                for (int g = 0; g < 4; g++)
                    mma8(o[g2][g], a0, a1, a2, a3, vb[g].x, vb[g].y);
            }
        }

        if (jt < 15)
            stKV(sm + ((jt + 1) & 1) * ABUF);
        __syncthreads();
    }

    // ---- final sum reduction + normalize + store ----
#pragma unroll
    for (int g2 = 0; g2 < 2; g2++) {
        l0[g2] += __shfl_xor_sync(0xffffffffu, l0[g2], 1);
        l0[g2] += __shfl_xor_sync(0xffffffffu, l0[g2], 2);
        l1[g2] += __shfl_xor_sync(0xffffffffu, l1[g2], 1);
        l1[g2] += __shfl_xor_sync(0xffffffffu, l1[g2], 2);
        const float il0 = 1.f / l0[g2], il1 = 1.f / l1[g2];
        const int m0 = wrp * 32 + g2 * 16;
#pragma unroll
        for (int g = 0; g < 4; g++) {
            const int dd = 8 * g + 2 * a4;
            float* p0 = g_att + (size_t)(h * 32 + dd) * NGLOB + qcol + m0 + r;
            float* p1 = p0 + NGLOB;
            p0[0] = o[g2][g][0] * il0;
            p1[0] = o[g2][g][1] * il0;
            p0[8] = o[g2][g][2] * il1;
            p1[8] = o[g2][g][3] * il1;
        }
    }
}

// ---------------------------------------------------------------------------
// 7x7 depthwise conv on V + attention output + b_pe -> g_t
// ---------------------------------------------------------------------------
__global__ void __launch_bounds__(256) dwconv_kernel(
    const float* __restrict__ wpe, const float* __restrict__ bpe)
{
    __shared__ float smv[70][72];
    __shared__ float wk[49];

    const int c = blockIdx.x, b = blockIdx.y;
    const int tid = threadIdx.x;

    for (int i = tid; i < 70 * 72; i += 256) (&smv[0][0])[i] = 0.f;
    if (tid < 49) wk[tid] = wpe[c * 49 + tid];
    __syncthreads();

    const int vrow = (c >> 5) * 96 + 64 + (c & 31);
    const float* vsrc = g_qkv + (size_t)vrow * NGLOB + b * 4096;
    const int r  = tid >> 2;
    const int c0 = (tid & 3) * 16;
#pragma unroll
    for (int q = 0; q < 16; q += 4) {
        float4 v = *(const float4*)(vsrc + r * 64 + c0 + q);
        smv[3 + r][3 + c0 + q + 0] = v.x;
        smv[3 + r][3 + c0 + q + 1] = v.y;
        smv[3 + r][3 + c0 + q + 2] = v.z;
        smv[3 + r][3 + c0 + q + 3] = v.w;
    }
    __syncthreads();

    const float* asrc = g_att + (size_t)c * NGLOB + b * 4096;
    const float bb = bpe[c];
    float out[16];
#pragma unroll
    for (int q = 0; q < 16; q += 4) {
        float4 a = *(const float4*)(asrc + r * 64 + c0 + q);
        out[q + 0] = a.x + bb; out[q + 1] = a.y + bb;
        out[q + 2] = a.z + bb; out[q + 3] = a.w + bb;
    }

#pragma unroll
    for (int ky = 0; ky < 7; ky++) {
        float row[22];
#pragma unroll
        for (int q = 0; q < 22; q++) row[q] = smv[r + ky][c0 + q];
#pragma unroll
        for (int kx = 0; kx < 7; kx++) {
            const float wv = wk[ky * 7 + kx];
#pragma unroll
            for (int xx = 0; xx < 16; xx++) out[xx] += wv * row[xx + kx];
        }
    }

    float* dst = g_t + (size_t)c * NGLOB + b * 4096 + r * 64 + c0;
#pragma unroll
    for (int q = 0; q < 16; q += 4)
        *(float4*)(dst + q) = make_float4(out[q], out[q + 1], out[q + 2], out[q + 3]);
}

// ---------------------------------------------------------------------------
extern "C" void kernel_launch(void* const* d_in, const int* in_sizes, int n_in,
                              void* d_out, int out_size)
{
    (void)in_sizes; (void)n_in; (void)out_size;
    const float* x      = (const float*)d_in[0];
    const float* w_qkv  = (const float*)d_in[1];
    const float* b_qkv  = (const float*)d_in[2];
    const float* w_pe   = (const float*)d_in[3];
    const float* b_pe   = (const float*)d_in[4];
    const float* w_proj = (const float*)d_in[5];
    const float* b_proj = (const float*)d_in[6];
    float* out = (float*)d_out;

    float* g_qkv_p; cudaGetSymbolAddress((void**)&g_qkv_p, g_qkv);
    float* g_t_p;   cudaGetSymbolAddress((void**)&g_t_p, g_t);

    cudaFuncSetAttribute(gemm_tf32_kernel,
                         cudaFuncAttributeMaxDynamicSharedMemorySize, GSMEM_BYTES);

    gemm_tf32_kernel<<<dim3(NGLOB / 128, C3 / 128), 256, GSMEM_BYTES>>>(
        w_qkv, b_qkv, x, 256 * 4096, 4096, g_qkv_p, 4096, NGLOB);

    attn_kernel<<<dim3(8, 8, 16), 128>>>();

    dwconv_kernel<<<dim3(CIN, 4), 256>>>(w_pe, b_pe);

    gemm_tf32_kernel<<<dim3(NGLOB / 128, CIN / 128), 256, GSMEM_BYTES>>>(
        w_proj, b_proj, g_t_p, 4096, NGLOB, out, 256 * 4096, 4096);
}